// round 1
// baseline (speedup 1.0000x reference)
#include <cuda_runtime.h>
#include <cuda_bf16.h>

// Problem constants (fixed shapes from setup_inputs)
constexpr int B    = 4;
constexpr int S    = 2048;
constexpr int N    = B * S;        // 8192
constexpr int KNEG = 4;
constexpr int NK   = N * KNEG;     // 32768
constexpr int WMAX = 16;

#define SOFT 1e-6f
#define EPSF 1e-9f

// force kernel tiling
constexpr int TPB   = 128;         // threads per block
constexpr int ITEMS = 2;           // i-rows per thread
constexpr int ITILE = TPB * ITEMS; // 256 i per block
constexpr int JS    = 16;          // j splits
constexpr int JC    = S / JS;      // 128 j per block

// deterministic scratch (no atomics)
__device__ __align__(16) float g_fpart[(size_t)JS * N * 2];

constexpr int LB = 64;             // loss partial blocks
__device__ __align__(16) float g_lpart[LB * 8];

// ---------------------------------------------------------------------------
// Force partial: grid (JS, S/ITILE, B), block TPB.
// Each thread accumulates forces for ITEMS i-rows over a JC-sized j chunk.
// ---------------------------------------------------------------------------
__global__ __launch_bounds__(TPB)
void force_partial_kernel(const float* __restrict__ pos,
                          const float* __restrict__ mass,
                          const float* __restrict__ G_,
                          const float* __restrict__ rep_)
{
    __shared__ float4 tile[JC];

    const int b     = blockIdx.z;
    const int i0    = blockIdx.y * ITILE + threadIdx.x;
    const int jbase = blockIdx.x * JC;

    const float Gp   = fmaxf(G_[0], 0.0f);
    const float reps = fmaxf(rep_[0], 0.0f);

    // stage j chunk (JC == TPB)
    {
        const int j = jbase + threadIdx.x;
        float2 p = __ldg(&((const float2*)pos)[b * S + j]);
        tile[threadIdx.x] = make_float4(p.x, p.y, __ldg(&mass[b * S + j]), 0.0f);
    }
    __syncthreads();

    float xi[ITEMS], yi[ITEMS], gm[ITEMS];
    float fx[ITEMS], fy[ITEMS];
#pragma unroll
    for (int t = 0; t < ITEMS; t++) {
        const int i = i0 + t * TPB;
        float2 p = __ldg(&((const float2*)pos)[b * S + i]);
        xi[t] = p.x; yi[t] = p.y;
        gm[t] = Gp * __ldg(&mass[b * S + i]);
        fx[t] = 0.0f; fy[t] = 0.0f;
    }

#pragma unroll 4
    for (int jj = 0; jj < JC; jj++) {
        const float4 sj = tile[jj];   // broadcast read, conflict-free
#pragma unroll
        for (int t = 0; t < ITEMS; t++) {
            const float dx = sj.x - xi[t];
            const float dy = sj.y - yi[t];
            const float d2 = fmaf(dx, dx, fmaf(dy, dy, SOFT));
            const float inv  = rsqrtf(d2);       // 1/dist
            const float dist = d2 * inv;
            // attractive = Gp*mi*mj / d2
            const float att = gm[t] * sj.z * (inv * inv);
            // repulsive = reps * relu(1 - dist/0.1) / (d2*dist + eps)
            const float trel = fmaxf(fmaf(dist, -10.0f, 1.0f), 0.0f);
            const float rep  = reps * trel * __frcp_rn(fmaf(d2, dist, EPSF));
            // force = (rep - att) * diff / dist   (eps vs dist>=1e-3 negligible)
            const float mg = (rep - att) * inv;
            fx[t] = fmaf(mg, dx, fx[t]);
            fy[t] = fmaf(mg, dy, fy[t]);
        }
    }

#pragma unroll
    for (int t = 0; t < ITEMS; t++) {
        const int gi = b * S + i0 + t * TPB;
        float2* o = (float2*)&g_fpart[((size_t)blockIdx.x * N + gi) * 2];
        *o = make_float2(fx[t], fy[t]);
    }
}

// ---------------------------------------------------------------------------
// Force reduce: sum JS partials per (i, component), write forces to d_out.
// ---------------------------------------------------------------------------
__global__ void force_reduce_kernel(float* __restrict__ out)
{
    const int idx = blockIdx.x * blockDim.x + threadIdx.x;  // over N*2
    if (idx >= N * 2) return;
    float s = 0.0f;
#pragma unroll
    for (int js = 0; js < JS; js++)
        s += g_fpart[(size_t)js * (N * 2) + idx];
    out[idx] = s;
}

// ---------------------------------------------------------------------------
// Loss partials. Sums needed:
//  s1 = sum_i m_i*pm_i / (||p_i - pp_i|| + eps)                 [N]
//  s2 = sum_n em_n*nm_n / (||p_{n/K} - np_n|| + eps)            [NK]
//  s3 = sum_i mind2(pos8_i)                                     [N]
//  s4 = sum_i mind2(pp8_i)                                      [N]
//  s5 = sum_n mind2(np8_n)                                      [NK]
//  s6 = sum_i m_i                                               [N]
//  s7 = sum_i |v_i|^2                                           [N]
// Entropy term cancels in F_pos - F_neg: variance never computed.
// ---------------------------------------------------------------------------
__device__ __forceinline__ float mind2_row(const float4 a, const float4 b4,
                                           const float* __restrict__ wsh, int W)
{
    float best = 3.4e38f;
    for (int w = 0; w < W; w++) {
        const float* wc = &wsh[w * 8];
        float d = 0.0f;
        float t;
        t = a.x  - wc[0]; d = fmaf(t, t, d);
        t = a.y  - wc[1]; d = fmaf(t, t, d);
        t = a.z  - wc[2]; d = fmaf(t, t, d);
        t = a.w  - wc[3]; d = fmaf(t, t, d);
        t = b4.x - wc[4]; d = fmaf(t, t, d);
        t = b4.y - wc[5]; d = fmaf(t, t, d);
        t = b4.z - wc[6]; d = fmaf(t, t, d);
        t = b4.w - wc[7]; d = fmaf(t, t, d);
        best = fminf(best, d);
    }
    return best;   // min(dist)^2 == min(dist^2)
}

__global__ __launch_bounds__(256)
void loss_partial_kernel(const float* __restrict__ pos2d,
                         const float* __restrict__ mass,
                         const float* __restrict__ vel,
                         const float* __restrict__ pos8,
                         const float* __restrict__ pp2d,
                         const float* __restrict__ pp8,
                         const float* __restrict__ pmass,
                         const float* __restrict__ np2d,
                         const float* __restrict__ np8,
                         const float* __restrict__ nmass,
                         const float* __restrict__ emass,
                         const float* __restrict__ wells,
                         int W)
{
    __shared__ float wsh[WMAX * 8];
    __shared__ float red[8][8];   // [warp][sum]

    const int tid = threadIdx.x;
    if (tid < W * 8) wsh[tid] = wells[tid];
    __syncthreads();

    float s1 = 0.f, s2 = 0.f, s3 = 0.f, s4 = 0.f, s5 = 0.f, s6 = 0.f, s7 = 0.f;

    const int stride = gridDim.x * blockDim.x;

    // ---- N-domain ----
    for (int i = blockIdx.x * blockDim.x + tid; i < N; i += stride) {
        float2 p = ((const float2*)pos2d)[i];
        float2 q = ((const float2*)pp2d)[i];
        float dx = p.x - q.x, dy = p.y - q.y;
        float dist = sqrtf(fmaf(dx, dx, dy * dy)) + EPSF;
        float m = mass[i];
        s1 += m * pmass[i] / dist;
        s6 += m;
        float2 v = ((const float2*)vel)[i];
        s7 = fmaf(v.x, v.x, fmaf(v.y, v.y, s7));

        float4 a  = ((const float4*)pos8)[i * 2];
        float4 b4 = ((const float4*)pos8)[i * 2 + 1];
        s3 += mind2_row(a, b4, wsh, W);
        a  = ((const float4*)pp8)[i * 2];
        b4 = ((const float4*)pp8)[i * 2 + 1];
        s4 += mind2_row(a, b4, wsh, W);
    }

    // ---- NK-domain ----
    for (int n = blockIdx.x * blockDim.x + tid; n < NK; n += stride) {
        float2 p = ((const float2*)pos2d)[n / KNEG];
        float2 q = ((const float2*)np2d)[n];
        float dx = p.x - q.x, dy = p.y - q.y;
        float dist = sqrtf(fmaf(dx, dx, dy * dy)) + EPSF;
        s2 += emass[n] * nmass[n] / dist;

        float4 a  = ((const float4*)np8)[n * 2];
        float4 b4 = ((const float4*)np8)[n * 2 + 1];
        s5 += mind2_row(a, b4, wsh, W);
    }

    // ---- block reduce 7 sums ----
    float vals[7] = {s1, s2, s3, s4, s5, s6, s7};
#pragma unroll
    for (int k = 0; k < 7; k++) {
#pragma unroll
        for (int off = 16; off > 0; off >>= 1)
            vals[k] += __shfl_down_sync(0xffffffffu, vals[k], off);
    }
    const int warp = tid >> 5;
    const int lane = tid & 31;
    if (lane == 0) {
#pragma unroll
        for (int k = 0; k < 7; k++) red[warp][k] = vals[k];
    }
    __syncthreads();
    if (warp == 0) {
#pragma unroll
        for (int k = 0; k < 7; k++) {
            float v = (lane < 8) ? red[lane][k] : 0.0f;
#pragma unroll
            for (int off = 4; off > 0; off >>= 1)
                v += __shfl_down_sync(0xffffffffu, v, off);
            if (lane == 0) g_lpart[blockIdx.x * 8 + k] = v;
        }
    }
}

// ---------------------------------------------------------------------------
// Final: combine partials, compute loss scalar -> d_out[N*2]
// ---------------------------------------------------------------------------
__global__ void loss_final_kernel(float* __restrict__ out,
                                  const float* __restrict__ G_,
                                  const float* __restrict__ ws_)
{
    __shared__ float sh[LB][8];
    const int tid = threadIdx.x;
    if (tid < LB) {
#pragma unroll
        for (int k = 0; k < 7; k++) sh[tid][k] = g_lpart[tid * 8 + k];
    }
    __syncthreads();
    if (tid == 0) {
        float s[7] = {0, 0, 0, 0, 0, 0, 0};
        for (int bI = 0; bI < LB; bI++)
#pragma unroll
            for (int k = 0; k < 7; k++) s[k] += sh[bI][k];

        const float Gp = fmaxf(G_[0], 0.0f);
        const float ws = fmaxf(ws_[0], 0.0f);

        const float S1 = s[0], S2 = s[1], S3 = s[2], S4 = s[3],
                    S5 = s[4], S6 = s[5], S7 = s[6];

        const float U_pos = -Gp * (S1 / (float)N) + ws * (S3 + S4) / (2.0f * (float)N);
        const float U_neg = -Gp * (S2 / (float)NK) +
                            ws * ((float)KNEG * S3 + S5) / (2.0f * (float)NK);
        // entropy term cancels in F_pos - F_neg
        const float fe = fmaxf(1.0f + U_pos - U_neg, 0.0f);
        const float ke = 1e-3f * 0.5f * (S6 / (float)N) * (S7 / (float)N);
        out[N * 2] = fe + ke;
    }
}

// ---------------------------------------------------------------------------
extern "C" void kernel_launch(void* const* d_in, const int* in_sizes, int n_in,
                              void* d_out, int out_size)
{
    const float* positions_2d = (const float*)d_in[0];
    const float* masses       = (const float*)d_in[1];
    const float* vel_2d       = (const float*)d_in[2];
    const float* pos_8d       = (const float*)d_in[3];
    const float* pos_pos_2d   = (const float*)d_in[4];
    const float* pos_pos_8d   = (const float*)d_in[5];
    const float* positive_m   = (const float*)d_in[6];
    const float* neg_pos_2d   = (const float*)d_in[7];
    const float* neg_pos_8d   = (const float*)d_in[8];
    const float* neg_masses   = (const float*)d_in[9];
    const float* exp_masses   = (const float*)d_in[10];
    const float* G            = (const float*)d_in[11];
    const float* rep_strength = (const float*)d_in[12];
    const float* well_centers = (const float*)d_in[13];
    const float* well_str     = (const float*)d_in[14];
    // temperature (15) / entropy_coeff (16) unused: entropy cancels in the loss.

    const int W = in_sizes[13] / 8;

    float* out = (float*)d_out;

    dim3 fgrid(JS, S / ITILE, B);
    force_partial_kernel<<<fgrid, TPB>>>(positions_2d, masses, G, rep_strength);
    force_reduce_kernel<<<(N * 2 + 255) / 256, 256>>>(out);

    loss_partial_kernel<<<LB, 256>>>(positions_2d, masses, vel_2d, pos_8d,
                                     pos_pos_2d, pos_pos_8d, positive_m,
                                     neg_pos_2d, neg_pos_8d, neg_masses,
                                     exp_masses, well_centers, W);
    loss_final_kernel<<<1, 256>>>(out, G, well_str);
}

// round 2
// speedup vs baseline: 1.0626x; 1.0626x over previous
#include <cuda_runtime.h>
#include <cuda_bf16.h>

// Problem constants (fixed shapes from setup_inputs)
constexpr int B    = 4;
constexpr int S    = 2048;
constexpr int N    = B * S;        // 8192
constexpr int KNEG = 4;
constexpr int NK   = N * KNEG;     // 32768
constexpr int WMAX = 16;

#define SOFT 1e-6f
#define EPSF 1e-9f

constexpr int LB = 64;             // loss partial blocks
__device__ __align__(16) float g_lpart[LB * 8];

// ---------------------------------------------------------------------------
// Loss partials. Sums needed:
//  s1 = sum_i m_i*pm_i / (||p_i - pp_i|| + eps)                 [N]
//  s2 = sum_n em_n*nm_n / (||p_{n/K} - np_n|| + eps)            [NK]
//  s3 = sum_i mind2(pos8_i)      s4 = sum_i mind2(pp8_i)        [N]
//  s5 = sum_n mind2(np8_n)                                      [NK]
//  s6 = sum_i m_i                s7 = sum_i |v_i|^2             [N]
// Entropy term cancels in F_pos - F_neg: variance never computed.
// ---------------------------------------------------------------------------
__device__ __forceinline__ float mind2_row(const float4 a, const float4 b4,
                                           const float* __restrict__ wsh, int W)
{
    float best = 3.4e38f;
    for (int w = 0; w < W; w++) {
        const float* wc = &wsh[w * 8];
        float d = 0.0f;
        float t;
        t = a.x  - wc[0]; d = fmaf(t, t, d);
        t = a.y  - wc[1]; d = fmaf(t, t, d);
        t = a.z  - wc[2]; d = fmaf(t, t, d);
        t = a.w  - wc[3]; d = fmaf(t, t, d);
        t = b4.x - wc[4]; d = fmaf(t, t, d);
        t = b4.y - wc[5]; d = fmaf(t, t, d);
        t = b4.z - wc[6]; d = fmaf(t, t, d);
        t = b4.w - wc[7]; d = fmaf(t, t, d);
        best = fminf(best, d);
    }
    return best;   // min(dist)^2 == min(dist^2)
}

__global__ __launch_bounds__(256)
void loss_partial_kernel(const float* __restrict__ pos2d,
                         const float* __restrict__ mass,
                         const float* __restrict__ vel,
                         const float* __restrict__ pos8,
                         const float* __restrict__ pp2d,
                         const float* __restrict__ pp8,
                         const float* __restrict__ pmass,
                         const float* __restrict__ np2d,
                         const float* __restrict__ np8,
                         const float* __restrict__ nmass,
                         const float* __restrict__ emass,
                         const float* __restrict__ wells,
                         int W)
{
    __shared__ float wsh[WMAX * 8];
    __shared__ float red[8][8];   // [warp][sum]

    const int tid = threadIdx.x;
    if (tid < W * 8) wsh[tid] = wells[tid];
    __syncthreads();

    float s1 = 0.f, s2 = 0.f, s3 = 0.f, s4 = 0.f, s5 = 0.f, s6 = 0.f, s7 = 0.f;

    const int stride = gridDim.x * blockDim.x;

    // ---- N-domain ----
    for (int i = blockIdx.x * blockDim.x + tid; i < N; i += stride) {
        float2 p = ((const float2*)pos2d)[i];
        float2 q = ((const float2*)pp2d)[i];
        float dx = p.x - q.x, dy = p.y - q.y;
        float dist = sqrtf(fmaf(dx, dx, dy * dy)) + EPSF;
        float m = mass[i];
        s1 += m * pmass[i] / dist;
        s6 += m;
        float2 v = ((const float2*)vel)[i];
        s7 = fmaf(v.x, v.x, fmaf(v.y, v.y, s7));

        float4 a  = ((const float4*)pos8)[i * 2];
        float4 b4 = ((const float4*)pos8)[i * 2 + 1];
        s3 += mind2_row(a, b4, wsh, W);
        a  = ((const float4*)pp8)[i * 2];
        b4 = ((const float4*)pp8)[i * 2 + 1];
        s4 += mind2_row(a, b4, wsh, W);
    }

    // ---- NK-domain ----
    for (int n = blockIdx.x * blockDim.x + tid; n < NK; n += stride) {
        float2 p = ((const float2*)pos2d)[n / KNEG];
        float2 q = ((const float2*)np2d)[n];
        float dx = p.x - q.x, dy = p.y - q.y;
        float dist = sqrtf(fmaf(dx, dx, dy * dy)) + EPSF;
        s2 += emass[n] * nmass[n] / dist;

        float4 a  = ((const float4*)np8)[n * 2];
        float4 b4 = ((const float4*)np8)[n * 2 + 1];
        s5 += mind2_row(a, b4, wsh, W);
    }

    // ---- block reduce 7 sums ----
    float vals[7] = {s1, s2, s3, s4, s5, s6, s7};
#pragma unroll
    for (int k = 0; k < 7; k++) {
#pragma unroll
        for (int off = 16; off > 0; off >>= 1)
            vals[k] += __shfl_down_sync(0xffffffffu, vals[k], off);
    }
    const int warp = tid >> 5;
    const int lane = tid & 31;
    if (lane == 0) {
#pragma unroll
        for (int k = 0; k < 7; k++) red[warp][k] = vals[k];
    }
    __syncthreads();
    if (warp == 0) {
#pragma unroll
        for (int k = 0; k < 7; k++) {
            float v = (lane < 8) ? red[lane][k] : 0.0f;
#pragma unroll
            for (int off = 4; off > 0; off >>= 1)
                v += __shfl_down_sync(0xffffffffu, v, off);
            if (lane == 0) g_lpart[blockIdx.x * 8 + k] = v;
        }
    }
}

// ---------------------------------------------------------------------------
// Force kernel: grid (S/32, B), block 256.
// Each CTA: 32 i-rows (one per lane), 8 warps each cover a 256-j slice of the
// full S=2048 batch staged in shared memory. No global partials, no 2nd pass.
// Block (0,0) additionally folds the loss-final reduction (g_lpart written by
// the loss_partial kernel, which precedes this one in the stream).
// ---------------------------------------------------------------------------
constexpr int FTPB = 256;
constexpr int FNW  = FTPB / 32;    // 8 warps
constexpr int JPW  = S / FNW;      // 256 j per warp

__global__ __launch_bounds__(FTPB)
void force_kernel(const float* __restrict__ pos,
                  const float* __restrict__ mass,
                  const float* __restrict__ G_,
                  const float* __restrict__ rep_,
                  const float* __restrict__ ws_,
                  float* __restrict__ out)
{
    __shared__ float2 sp[S];       // 16 KB
    __shared__ float  smass[S];    //  8 KB
    __shared__ float2 red[FNW][32];

    const int tid  = threadIdx.x;
    const int lane = tid & 31;
    const int warp = tid >> 5;
    const int b    = blockIdx.y;
    const int i0   = blockIdx.x * 32;

    const float Gp   = fmaxf(G_[0], 0.0f);
    const float reps = fmaxf(rep_[0], 0.0f);
    const float c1   = -10.0f * reps;  // fold reps into relu coeffs
    const float c0   = reps;

    // stage full batch (pos + mass) in shared
    for (int j = tid; j < S; j += FTPB) {
        sp[j]    = __ldg(&((const float2*)pos)[b * S + j]);
        smass[j] = __ldg(&mass[b * S + j]);
    }
    __syncthreads();

    const float2 pi = sp[i0 + lane];
    const float  gm = Gp * smass[i0 + lane];

    float fx = 0.0f, fy = 0.0f;
    const int jbeg = warp * JPW;

#pragma unroll 4
    for (int jj = 0; jj < JPW; jj++) {
        const int j = jbeg + jj;
        const float2 pj = sp[j];       // broadcast (all lanes same j)
        const float  mj = smass[j];
        const float dx = pj.x - pi.x;
        const float dy = pj.y - pi.y;
        const float d2 = fmaf(dx, dx, fmaf(dy, dy, SOFT));
        const float u  = rsqrtf(d2);              // 1/dist
        const float d  = d2 * u;                  // dist
        const float gmm = gm * mj;
        const float t   = fmaxf(fmaf(d, c1, c0), 0.0f);     // reps*relu(1-10d)
        const float r   = __frcp_rn(fmaf(d2, d, EPSF));     // 1/(d^3+eps)
        const float rep = t * r;
        const float att = gmm * (u * u);
        const float mg  = (rep - att) * u;
        fx = fmaf(mg, dx, fx);
        fy = fmaf(mg, dy, fy);
    }

    red[warp][lane] = make_float2(fx, fy);
    __syncthreads();

    if (warp == 0) {
        float sx = 0.0f, sy = 0.0f;
#pragma unroll
        for (int w = 0; w < FNW; w++) {
            sx += red[w][lane].x;
            sy += red[w][lane].y;
        }
        ((float2*)out)[b * S + i0 + lane] = make_float2(sx, sy);
    }

    // ---- loss final (block (0,0) only; g_lpart written by prior kernel) ----
    if (blockIdx.x == 0 && blockIdx.y == 0) {
        __syncthreads();   // red[] reuse
        float v[7] = {0, 0, 0, 0, 0, 0, 0};
        if (tid < LB) {
#pragma unroll
            for (int k = 0; k < 7; k++) v[k] = g_lpart[tid * 8 + k];
        }
#pragma unroll
        for (int k = 0; k < 7; k++) {
#pragma unroll
            for (int off = 16; off > 0; off >>= 1)
                v[k] += __shfl_down_sync(0xffffffffu, v[k], off);
        }
        if (lane == 0 && warp < (LB / 32)) {
#pragma unroll
            for (int k = 0; k < 7; k++) red[warp][k].x = v[k];
        }
        __syncthreads();
        if (tid == 0) {
            float s[7];
#pragma unroll
            for (int k = 0; k < 7; k++) s[k] = red[0][k].x + red[1][k].x;

            const float ws = fmaxf(ws_[0], 0.0f);
            const float S1 = s[0], S2 = s[1], S3 = s[2], S4 = s[3],
                        S5 = s[4], S6 = s[5], S7 = s[6];

            const float U_pos = -Gp * (S1 / (float)N) +
                                ws * (S3 + S4) / (2.0f * (float)N);
            const float U_neg = -Gp * (S2 / (float)NK) +
                                ws * ((float)KNEG * S3 + S5) / (2.0f * (float)NK);
            // entropy term cancels in F_pos - F_neg
            const float fe = fmaxf(1.0f + U_pos - U_neg, 0.0f);
            const float ke = 1e-3f * 0.5f * (S6 / (float)N) * (S7 / (float)N);
            out[N * 2] = fe + ke;
        }
    }
}

// ---------------------------------------------------------------------------
extern "C" void kernel_launch(void* const* d_in, const int* in_sizes, int n_in,
                              void* d_out, int out_size)
{
    const float* positions_2d = (const float*)d_in[0];
    const float* masses       = (const float*)d_in[1];
    const float* vel_2d       = (const float*)d_in[2];
    const float* pos_8d       = (const float*)d_in[3];
    const float* pos_pos_2d   = (const float*)d_in[4];
    const float* pos_pos_8d   = (const float*)d_in[5];
    const float* positive_m   = (const float*)d_in[6];
    const float* neg_pos_2d   = (const float*)d_in[7];
    const float* neg_pos_8d   = (const float*)d_in[8];
    const float* neg_masses   = (const float*)d_in[9];
    const float* exp_masses   = (const float*)d_in[10];
    const float* G            = (const float*)d_in[11];
    const float* rep_strength = (const float*)d_in[12];
    const float* well_centers = (const float*)d_in[13];
    const float* well_str     = (const float*)d_in[14];
    // temperature (15) / entropy_coeff (16) unused: entropy cancels.

    const int W = in_sizes[13] / 8;
    float* out = (float*)d_out;

    // loss partials first: force_kernel's block (0,0) consumes g_lpart
    loss_partial_kernel<<<LB, 256>>>(positions_2d, masses, vel_2d, pos_8d,
                                     pos_pos_2d, pos_pos_8d, positive_m,
                                     neg_pos_2d, neg_pos_8d, neg_masses,
                                     exp_masses, well_centers, W);

    dim3 fgrid(S / 32, B);
    force_kernel<<<fgrid, FTPB>>>(positions_2d, masses, G, rep_strength,
                                  well_str, out);
}

// round 3
// speedup vs baseline: 1.7033x; 1.6030x over previous
#include <cuda_runtime.h>
#include <cuda_bf16.h>

// Problem constants (fixed shapes from setup_inputs)
constexpr int B    = 4;
constexpr int S    = 2048;
constexpr int N    = B * S;        // 8192
constexpr int KNEG = 4;
constexpr int NK   = N * KNEG;     // 32768
constexpr int WMAX = 16;

#define SOFT 1e-6f
#define EPSF 1e-9f

constexpr int LB = 128;            // loss partial blocks
__device__ __align__(16) float g_lpart[LB * 8];

// ---------------------------------------------------------------------------
// Loss partials (entropy term cancels in F_pos - F_neg; never computed).
// ---------------------------------------------------------------------------
__device__ __forceinline__ float mind2_row(const float4 a, const float4 b4,
                                           const float* __restrict__ wsh, int W)
{
    float best = 3.4e38f;
    for (int w = 0; w < W; w++) {
        const float* wc = &wsh[w * 8];
        float d = 0.0f;
        float t;
        t = a.x  - wc[0]; d = fmaf(t, t, d);
        t = a.y  - wc[1]; d = fmaf(t, t, d);
        t = a.z  - wc[2]; d = fmaf(t, t, d);
        t = a.w  - wc[3]; d = fmaf(t, t, d);
        t = b4.x - wc[4]; d = fmaf(t, t, d);
        t = b4.y - wc[5]; d = fmaf(t, t, d);
        t = b4.z - wc[6]; d = fmaf(t, t, d);
        t = b4.w - wc[7]; d = fmaf(t, t, d);
        best = fminf(best, d);
    }
    return best;   // min(dist)^2 == min(dist^2)
}

__global__ __launch_bounds__(256)
void loss_partial_kernel(const float* __restrict__ pos2d,
                         const float* __restrict__ mass,
                         const float* __restrict__ vel,
                         const float* __restrict__ pos8,
                         const float* __restrict__ pp2d,
                         const float* __restrict__ pp8,
                         const float* __restrict__ pmass,
                         const float* __restrict__ np2d,
                         const float* __restrict__ np8,
                         const float* __restrict__ nmass,
                         const float* __restrict__ emass,
                         const float* __restrict__ wells,
                         int W)
{
    __shared__ float wsh[WMAX * 8];
    __shared__ float red[8][8];   // [warp][sum]

    const int tid = threadIdx.x;
    if (tid < W * 8) wsh[tid] = wells[tid];
    __syncthreads();

    float s1 = 0.f, s2 = 0.f, s3 = 0.f, s4 = 0.f, s5 = 0.f, s6 = 0.f, s7 = 0.f;
    const int stride = gridDim.x * blockDim.x;

    // ---- N-domain ----
    for (int i = blockIdx.x * blockDim.x + tid; i < N; i += stride) {
        float2 p = ((const float2*)pos2d)[i];
        float2 q = ((const float2*)pp2d)[i];
        float dx = p.x - q.x, dy = p.y - q.y;
        float dist = sqrtf(fmaf(dx, dx, dy * dy)) + EPSF;
        float m = mass[i];
        s1 += m * pmass[i] / dist;
        s6 += m;
        float2 v = ((const float2*)vel)[i];
        s7 = fmaf(v.x, v.x, fmaf(v.y, v.y, s7));

        float4 a  = ((const float4*)pos8)[i * 2];
        float4 b4 = ((const float4*)pos8)[i * 2 + 1];
        s3 += mind2_row(a, b4, wsh, W);
        a  = ((const float4*)pp8)[i * 2];
        b4 = ((const float4*)pp8)[i * 2 + 1];
        s4 += mind2_row(a, b4, wsh, W);
    }

    // ---- NK-domain ----
    for (int n = blockIdx.x * blockDim.x + tid; n < NK; n += stride) {
        float2 p = ((const float2*)pos2d)[n / KNEG];
        float2 q = ((const float2*)np2d)[n];
        float dx = p.x - q.x, dy = p.y - q.y;
        float dist = sqrtf(fmaf(dx, dx, dy * dy)) + EPSF;
        s2 += emass[n] * nmass[n] / dist;

        float4 a  = ((const float4*)np8)[n * 2];
        float4 b4 = ((const float4*)np8)[n * 2 + 1];
        s5 += mind2_row(a, b4, wsh, W);
    }

    float vals[7] = {s1, s2, s3, s4, s5, s6, s7};
#pragma unroll
    for (int k = 0; k < 7; k++) {
#pragma unroll
        for (int off = 16; off > 0; off >>= 1)
            vals[k] += __shfl_down_sync(0xffffffffu, vals[k], off);
    }
    const int warp = tid >> 5;
    const int lane = tid & 31;
    if (lane == 0) {
#pragma unroll
        for (int k = 0; k < 7; k++) red[warp][k] = vals[k];
    }
    __syncthreads();
    if (warp == 0) {
#pragma unroll
        for (int k = 0; k < 7; k++) {
            float v = (lane < 8) ? red[lane][k] : 0.0f;
#pragma unroll
            for (int off = 4; off > 0; off >>= 1)
                v += __shfl_down_sync(0xffffffffu, v, off);
            if (lane == 0) g_lpart[blockIdx.x * 8 + k] = v;
        }
    }
}

// ---------------------------------------------------------------------------
// Force kernel: grid (S/32, B), block 512 (16 warps).
// Each CTA: 32 i-rows (one per lane); each warp covers a 128-j slice of the
// full batch staged as float4 (x, y, mass) in shared memory.
// Repulsive branch is warp-uniformly skipped when all lanes have d >= CUTOFF
// (~92% of warp-iterations for N(0,1) positions).
// Block (0,0) folds the final loss reduction from g_lpart.
// ---------------------------------------------------------------------------
constexpr int FTPB = 512;
constexpr int FNW  = FTPB / 32;    // 16 warps
constexpr int JPW  = S / FNW;      // 128 j per warp

__global__ __launch_bounds__(FTPB)
void force_kernel(const float* __restrict__ pos,
                  const float* __restrict__ mass,
                  const float* __restrict__ G_,
                  const float* __restrict__ rep_,
                  const float* __restrict__ ws_,
                  float* __restrict__ out)
{
    __shared__ float4 tile[S];           // 32 KB (x, y, mass, pad)
    __shared__ float2 red[FNW][32];      // 4 KB

    const int tid  = threadIdx.x;
    const int lane = tid & 31;
    const int warp = tid >> 5;
    const int b    = blockIdx.y;
    const int i0   = blockIdx.x * 32;

    const float Gp   = fmaxf(G_[0], 0.0f);
    const float reps = fmaxf(rep_[0], 0.0f);
    const float c1   = -10.0f * reps;    // reps * relu(1 - d/0.1) = max(c1*d+c0, 0)
    const float c0   = reps;

    for (int j = tid; j < S; j += FTPB) {
        float2 p = __ldg(&((const float2*)pos)[b * S + j]);
        tile[j] = make_float4(p.x, p.y, __ldg(&mass[b * S + j]), 0.0f);
    }
    __syncthreads();

    const float pix = tile[i0 + lane].x;
    const float piy = tile[i0 + lane].y;
    const float gm  = Gp * tile[i0 + lane].z;

    float fx = 0.0f, fy = 0.0f;
    const int jbeg = warp * JPW;

#pragma unroll 4
    for (int jj = 0; jj < JPW; jj++) {
        const float4 tj = tile[jbeg + jj];   // LDS.128 broadcast
        const float dx = tj.x - pix;
        const float dy = tj.y - piy;
        const float d2 = fmaf(dx, dx, fmaf(dy, dy, SOFT));
        const float u  = rsqrtf(d2);                 // 1/dist
        const float u2 = u * u;
        const float gmm = gm * tj.z;
        float mg = -(gmm * u2) * u;                  // (0 - att)/dist
        if (__any_sync(0xffffffffu, d2 < 0.01f)) {   // any lane inside CUTOFF
            const float d = d2 * u;
            const float t = fmaxf(fmaf(d, c1, c0), 0.0f);
            const float r = __fdividef(t, fmaf(d2, d, EPSF));  // rep magnitude
            mg = fmaf(r, u, mg);
        }
        fx = fmaf(mg, dx, fx);
        fy = fmaf(mg, dy, fy);
    }

    red[warp][lane] = make_float2(fx, fy);
    __syncthreads();

    if (warp == 0) {
        float sx = 0.0f, sy = 0.0f;
#pragma unroll
        for (int w = 0; w < FNW; w++) {
            sx += red[w][lane].x;
            sy += red[w][lane].y;
        }
        ((float2*)out)[b * S + i0 + lane] = make_float2(sx, sy);
    }

    // ---- loss final (block (0,0) only; g_lpart written by prior kernel) ----
    if (blockIdx.x == 0 && blockIdx.y == 0) {
        __syncthreads();   // red[] reuse
        float v[7] = {0, 0, 0, 0, 0, 0, 0};
        if (tid < LB) {
#pragma unroll
            for (int k = 0; k < 7; k++) v[k] = g_lpart[tid * 8 + k];
        }
#pragma unroll
        for (int k = 0; k < 7; k++) {
#pragma unroll
            for (int off = 16; off > 0; off >>= 1)
                v[k] += __shfl_down_sync(0xffffffffu, v[k], off);
        }
        if (lane == 0 && warp < (LB / 32)) {
#pragma unroll
            for (int k = 0; k < 7; k++) red[warp][k].x = v[k];
        }
        __syncthreads();
        if (tid == 0) {
            float s[7];
#pragma unroll
            for (int k = 0; k < 7; k++) {
                float acc = 0.0f;
#pragma unroll
                for (int w = 0; w < LB / 32; w++) acc += red[w][k].x;
                s[k] = acc;
            }

            const float ws = fmaxf(ws_[0], 0.0f);
            const float S1 = s[0], S2 = s[1], S3 = s[2], S4 = s[3],
                        S5 = s[4], S6 = s[5], S7 = s[6];

            const float U_pos = -Gp * (S1 / (float)N) +
                                ws * (S3 + S4) / (2.0f * (float)N);
            const float U_neg = -Gp * (S2 / (float)NK) +
                                ws * ((float)KNEG * S3 + S5) / (2.0f * (float)NK);
            const float fe = fmaxf(1.0f + U_pos - U_neg, 0.0f);
            const float ke = 1e-3f * 0.5f * (S6 / (float)N) * (S7 / (float)N);
            out[N * 2] = fe + ke;
        }
    }
}

// ---------------------------------------------------------------------------
extern "C" void kernel_launch(void* const* d_in, const int* in_sizes, int n_in,
                              void* d_out, int out_size)
{
    const float* positions_2d = (const float*)d_in[0];
    const float* masses       = (const float*)d_in[1];
    const float* vel_2d       = (const float*)d_in[2];
    const float* pos_8d       = (const float*)d_in[3];
    const float* pos_pos_2d   = (const float*)d_in[4];
    const float* pos_pos_8d   = (const float*)d_in[5];
    const float* positive_m   = (const float*)d_in[6];
    const float* neg_pos_2d   = (const float*)d_in[7];
    const float* neg_pos_8d   = (const float*)d_in[8];
    const float* neg_masses   = (const float*)d_in[9];
    const float* exp_masses   = (const float*)d_in[10];
    const float* G            = (const float*)d_in[11];
    const float* rep_strength = (const float*)d_in[12];
    const float* well_centers = (const float*)d_in[13];
    const float* well_str     = (const float*)d_in[14];
    // temperature (15) / entropy_coeff (16) unused: entropy cancels.

    const int W = in_sizes[13] / 8;
    float* out = (float*)d_out;

    loss_partial_kernel<<<LB, 256>>>(positions_2d, masses, vel_2d, pos_8d,
                                     pos_pos_2d, pos_pos_8d, positive_m,
                                     neg_pos_2d, neg_pos_8d, neg_masses,
                                     exp_masses, well_centers, W);

    dim3 fgrid(S / 32, B);
    force_kernel<<<fgrid, FTPB>>>(positions_2d, masses, G, rep_strength,
                                  well_str, out);
}

// round 4
// speedup vs baseline: 1.8902x; 1.1098x over previous
#include <cuda_runtime.h>
#include <cuda_bf16.h>

// Problem constants (fixed shapes from setup_inputs)
constexpr int B    = 4;
constexpr int S    = 2048;
constexpr int N    = B * S;        // 8192
constexpr int KNEG = 4;
constexpr int NK   = N * KNEG;     // 32768
constexpr int WMAX = 16;

#define SOFT 1e-6f
#define EPSF 1e-9f
#define CUT2 0.01f

constexpr int FB    = 256;           // force blocks (S/32 * B)
constexpr int LB    = 64;            // loss partial blocks
constexpr int TOTAL = FB + LB;       // 320 — single wave at <=3 CTA/SM
constexpr int TPB   = 512;           // 16 warps
constexpr int FNW   = TPB / 32;
constexpr int JPW   = S / FNW;       // 128 j per warp

__device__ __align__(16) float g_lpart[LB * 8];
__device__ unsigned int g_cnt;       // zero-init; reset by final block each run

// ---------------- approx MUFU + packed f32x2 helpers -----------------------
typedef unsigned long long u64;

__device__ __forceinline__ float rsq(float x) {
    float r; asm("rsqrt.approx.f32 %0, %1;" : "=f"(r) : "f"(x)); return r;
}
__device__ __forceinline__ float rcp(float x) {
    float r; asm("rcp.approx.f32 %0, %1;" : "=f"(r) : "f"(x)); return r;
}
__device__ __forceinline__ u64 pk(float lo, float hi) {
    u64 r; asm("mov.b64 %0, {%1, %2};" : "=l"(r) : "f"(lo), "f"(hi)); return r;
}
__device__ __forceinline__ void upk(float& lo, float& hi, u64 v) {
    asm("mov.b64 {%0, %1}, %2;" : "=f"(lo), "=f"(hi) : "l"(v));
}
__device__ __forceinline__ u64 add2(u64 a, u64 b) {
    u64 d; asm("add.rn.f32x2 %0, %1, %2;" : "=l"(d) : "l"(a), "l"(b)); return d;
}
__device__ __forceinline__ u64 mul2(u64 a, u64 b) {
    u64 d; asm("mul.rn.f32x2 %0, %1, %2;" : "=l"(d) : "l"(a), "l"(b)); return d;
}
__device__ __forceinline__ u64 fma2(u64 a, u64 b, u64 c) {
    u64 d; asm("fma.rn.f32x2 %0, %1, %2, %3;" : "=l"(d) : "l"(a), "l"(b), "l"(c)); return d;
}

// ---------------------------------------------------------------------------
__device__ __forceinline__ float mind2_row(const float4 a, const float4 b4,
                                           const float* __restrict__ wsh, int W)
{
    float best = 3.4e38f;
    for (int w = 0; w < W; w++) {
        const float* wc = &wsh[w * 8];
        float d = 0.0f, t;
        t = a.x  - wc[0]; d = fmaf(t, t, d);
        t = a.y  - wc[1]; d = fmaf(t, t, d);
        t = a.z  - wc[2]; d = fmaf(t, t, d);
        t = a.w  - wc[3]; d = fmaf(t, t, d);
        t = b4.x - wc[4]; d = fmaf(t, t, d);
        t = b4.y - wc[5]; d = fmaf(t, t, d);
        t = b4.z - wc[6]; d = fmaf(t, t, d);
        t = b4.w - wc[7]; d = fmaf(t, t, d);
        best = fminf(best, d);
    }
    return best;   // min(dist)^2 == min(dist^2)
}

// ---------------------------------------------------------------------------
// Fused kernel. Blocks [0,FB): force tiles. Blocks [FB,TOTAL): loss partials.
// Last-arriving block (threadfence + atomic ticket) folds the loss final.
// Entropy term cancels in F_pos - F_neg and is never computed.
// ---------------------------------------------------------------------------
__global__ __launch_bounds__(TPB)
void fused_kernel(const float* __restrict__ pos,
                  const float* __restrict__ mass,
                  const float* __restrict__ vel,
                  const float* __restrict__ pos8,
                  const float* __restrict__ pp2d,
                  const float* __restrict__ pp8,
                  const float* __restrict__ pmass,
                  const float* __restrict__ np2d,
                  const float* __restrict__ np8,
                  const float* __restrict__ nmass,
                  const float* __restrict__ emass,
                  const float* __restrict__ wells,
                  const float* __restrict__ G_,
                  const float* __restrict__ rep_,
                  const float* __restrict__ ws_,
                  int W,
                  float* __restrict__ out)
{
    __shared__ __align__(16) float sx[S], sy[S], sm[S];   // 24 KB
    __shared__ float2 red[FNW][32];                       // 4 KB
    __shared__ float wsh[WMAX * 8];
    __shared__ float lred[FNW][8];
    __shared__ unsigned s_last;

    const int tid  = threadIdx.x;
    const int lane = tid & 31;
    const int warp = tid >> 5;
    const float Gp = fmaxf(G_[0], 0.0f);

    if (blockIdx.x < FB) {
        // =================== FORCE TILE ===================
        const int b  = blockIdx.x >> 6;
        const int i0 = (blockIdx.x & 63) * 32;

        const float reps = fmaxf(rep_[0], 0.0f);
        const float c1   = -10.0f * reps;   // reps*relu(1-d/0.1) = max(c1*d+c0,0)
        const float c0   = reps;

        for (int j = tid; j < S; j += TPB) {
            float2 p = ((const float2*)pos)[b * S + j];
            sx[j] = p.x; sy[j] = p.y;
            sm[j] = mass[b * S + j];
        }
        __syncthreads();

        const float pix = sx[i0 + lane];
        const float piy = sy[i0 + lane];
        const float gm  = Gp * sm[i0 + lane];

        const u64 npx2  = pk(-pix, -pix);
        const u64 npy2  = pk(-piy, -piy);
        const u64 ngm2  = pk(-gm, -gm);
        const u64 soft2 = pk(SOFT, SOFT);

        const float2* sx2 = (const float2*)sx;
        const float2* sy2 = (const float2*)sy;
        const float2* sm2 = (const float2*)sm;
        const int hbeg = warp * (JPW / 2);

        u64 fx2 = 0ull, fy2 = 0ull;

#pragma unroll 4
        for (int h = 0; h < JPW / 2; h++) {
            const float2 xj = sx2[hbeg + h];
            const float2 yj = sy2[hbeg + h];
            const float2 mj = sm2[hbeg + h];
            const u64 xp = pk(xj.x, xj.y);
            const u64 yp = pk(yj.x, yj.y);
            const u64 mp = pk(mj.x, mj.y);

            const u64 dx = add2(xp, npx2);
            const u64 dy = add2(yp, npy2);
            u64 d2 = fma2(dx, dx, soft2);
            d2 = fma2(dy, dy, d2);
            float d2a, d2b; upk(d2a, d2b, d2);
            const float ua = rsq(d2a);
            const float ub = rsq(d2b);
            const u64 up  = pk(ua, ub);
            const u64 gmm = mul2(ngm2, mp);     // -Gp*mi*mj (packed)
            const u64 u2p = mul2(up, up);
            u64 mg = mul2(gmm, u2p);
            mg = mul2(mg, up);                  // -att/dist

            if (__any_sync(0xffffffffu, fminf(d2a, d2b) < CUT2)) {
                float mga, mgb; upk(mga, mgb, mg);
                const float da = d2a * ua;
                const float ta = fmaxf(fmaf(da, c1, c0), 0.0f);
                mga = fmaf(ta * rcp(fmaf(d2a, da, EPSF)), ua, mga);
                const float db = d2b * ub;
                const float tb = fmaxf(fmaf(db, c1, c0), 0.0f);
                mgb = fmaf(tb * rcp(fmaf(d2b, db, EPSF)), ub, mgb);
                mg = pk(mga, mgb);
            }
            fx2 = fma2(mg, dx, fx2);
            fy2 = fma2(mg, dy, fy2);
        }

        float fxa, fxb, fya, fyb;
        upk(fxa, fxb, fx2);
        upk(fya, fyb, fy2);
        red[warp][lane] = make_float2(fxa + fxb, fya + fyb);
        __syncthreads();

        if (warp == 0) {
            float sxs = 0.0f, sys = 0.0f;
#pragma unroll
            for (int w = 0; w < FNW; w++) {
                sxs += red[w][lane].x;
                sys += red[w][lane].y;
            }
            ((float2*)out)[b * S + i0 + lane] = make_float2(sxs, sys);
        }
    } else {
        // =================== LOSS PARTIAL ===================
        const int lb = blockIdx.x - FB;
        if (tid < W * 8) wsh[tid] = wells[tid];
        __syncthreads();

        float s1 = 0.f, s2 = 0.f, s3 = 0.f, s4 = 0.f, s5 = 0.f, s6 = 0.f, s7 = 0.f;
        const int stride = LB * TPB;          // 32768

        for (int i = lb * TPB + tid; i < N; i += stride) {
            float2 p = ((const float2*)pos)[i];
            float2 q = ((const float2*)pp2d)[i];
            float dx = p.x - q.x, dy = p.y - q.y;
            float d2 = fmaf(dx, dx, dy * dy);
            float m = mass[i];
            s1 = fmaf(m * pmass[i], rsq(d2), s1);   // eps vs dist: <=1e-6 rel
            s6 += m;
            float2 v = ((const float2*)vel)[i];
            s7 = fmaf(v.x, v.x, fmaf(v.y, v.y, s7));

            float4 a  = ((const float4*)pos8)[i * 2];
            float4 b4 = ((const float4*)pos8)[i * 2 + 1];
            s3 += mind2_row(a, b4, wsh, W);
            a  = ((const float4*)pp8)[i * 2];
            b4 = ((const float4*)pp8)[i * 2 + 1];
            s4 += mind2_row(a, b4, wsh, W);
        }

        for (int n = lb * TPB + tid; n < NK; n += stride) {
            float2 p = ((const float2*)pos)[n / KNEG];
            float2 q = ((const float2*)np2d)[n];
            float dx = p.x - q.x, dy = p.y - q.y;
            float d2 = fmaf(dx, dx, dy * dy);
            s2 = fmaf(emass[n] * nmass[n], rsq(d2), s2);

            float4 a  = ((const float4*)np8)[n * 2];
            float4 b4 = ((const float4*)np8)[n * 2 + 1];
            s5 += mind2_row(a, b4, wsh, W);
        }

        float vals[7] = {s1, s2, s3, s4, s5, s6, s7};
#pragma unroll
        for (int k = 0; k < 7; k++) {
#pragma unroll
            for (int off = 16; off > 0; off >>= 1)
                vals[k] += __shfl_down_sync(0xffffffffu, vals[k], off);
        }
        if (lane == 0) {
#pragma unroll
            for (int k = 0; k < 7; k++) lred[warp][k] = vals[k];
        }
        __syncthreads();
        if (warp == 0) {
#pragma unroll
            for (int k = 0; k < 7; k++) {
                float v = (lane < FNW) ? lred[lane][k] : 0.0f;
#pragma unroll
                for (int off = 8; off > 0; off >>= 1)
                    v += __shfl_down_sync(0xffffffffu, v, off);
                if (lane == 0) g_lpart[lb * 8 + k] = v;
            }
        }
    }

    // =================== TICKET + LOSS FINAL ===================
    __syncthreads();
    if (tid == 0) {
        __threadfence();
        unsigned t = atomicAdd(&g_cnt, 1u);
        s_last = (t == TOTAL - 1) ? 1u : 0u;
    }
    __syncthreads();
    if (s_last) {
        __threadfence();
        if (warp == 0) {
            float s[7];
#pragma unroll
            for (int k = 0; k < 7; k++) {
                float v = g_lpart[lane * 8 + k] + g_lpart[(lane + 32) * 8 + k];
#pragma unroll
                for (int off = 16; off > 0; off >>= 1)
                    v += __shfl_down_sync(0xffffffffu, v, off);
                s[k] = v;   // valid on lane 0
            }
            if (lane == 0) {
                const float ws = fmaxf(ws_[0], 0.0f);
                const float S1 = s[0], S2 = s[1], S3 = s[2], S4 = s[3],
                            S5 = s[4], S6 = s[5], S7 = s[6];
                const float U_pos = -Gp * (S1 / (float)N) +
                                    ws * (S3 + S4) / (2.0f * (float)N);
                const float U_neg = -Gp * (S2 / (float)NK) +
                                    ws * ((float)KNEG * S3 + S5) / (2.0f * (float)NK);
                const float fe = fmaxf(1.0f + U_pos - U_neg, 0.0f);
                const float ke = 1e-3f * 0.5f * (S6 / (float)N) * (S7 / (float)N);
                out[N * 2] = fe + ke;
                g_cnt = 0;   // reset for next graph replay
            }
        }
    }
}

// ---------------------------------------------------------------------------
extern "C" void kernel_launch(void* const* d_in, const int* in_sizes, int n_in,
                              void* d_out, int out_size)
{
    const float* positions_2d = (const float*)d_in[0];
    const float* masses       = (const float*)d_in[1];
    const float* vel_2d       = (const float*)d_in[2];
    const float* pos_8d       = (const float*)d_in[3];
    const float* pos_pos_2d   = (const float*)d_in[4];
    const float* pos_pos_8d   = (const float*)d_in[5];
    const float* positive_m   = (const float*)d_in[6];
    const float* neg_pos_2d   = (const float*)d_in[7];
    const float* neg_pos_8d   = (const float*)d_in[8];
    const float* neg_masses   = (const float*)d_in[9];
    const float* exp_masses   = (const float*)d_in[10];
    const float* G            = (const float*)d_in[11];
    const float* rep_strength = (const float*)d_in[12];
    const float* well_centers = (const float*)d_in[13];
    const float* well_str     = (const float*)d_in[14];
    // temperature (15) / entropy_coeff (16) unused: entropy cancels.

    const int W = in_sizes[13] / 8;
    float* out = (float*)d_out;

    fused_kernel<<<TOTAL, TPB>>>(positions_2d, masses, vel_2d, pos_8d,
                                 pos_pos_2d, pos_pos_8d, positive_m,
                                 neg_pos_2d, neg_pos_8d, neg_masses,
                                 exp_masses, well_centers,
                                 G, rep_strength, well_str, W, out);
}